// round 15
// baseline (speedup 1.0000x reference)
#include <cuda_runtime.h>
#include <cuda_bf16.h>

#define NN 1000000
#define NE 16000000

// -------- scratch (device globals; no allocation allowed) --------
__device__ float2 g_aggc[NN];    // {sum of x[src], count}
__device__ float4 g_h1[NN];
__device__ float4 g_sum2[NN];
__device__ float4 g_h2[NN];
__device__ float2 g_p3[NN];      // h2 @ W3l (projected to dim 2 before scatter)
__device__ float2 g_sum3[NN];    // accumulated projected values
__device__ float  g_inv[NN];     // 1 / max(count, 1)

__device__ __forceinline__ void red_add_v2(float2* addr, float a, float b) {
    asm volatile("red.global.add.v2.f32 [%0], {%1, %2};"
                 :: "l"(addr), "f"(a), "f"(b) : "memory");
}
__device__ __forceinline__ void red_add_v4(float4* addr, float4 v) {
    asm volatile("red.global.add.v4.f32 [%0], {%1, %2, %3, %4};"
                 :: "l"(addr), "f"(v.x), "f"(v.y), "f"(v.z), "f"(v.w) : "memory");
}
// streaming (evict-first) load for the one-shot edge index stream
__device__ __forceinline__ int4 ldcs_int4(const int4* p) {
    int4 v;
    asm volatile("ld.global.cs.v4.s32 {%0,%1,%2,%3}, [%4];"
                 : "=r"(v.x), "=r"(v.y), "=r"(v.z), "=r"(v.w) : "l"(p));
    return v;
}
// L2 evict-last cache policy (valid for any width via cache_hint form)
__device__ __forceinline__ unsigned long long mk_evict_last_policy() {
    unsigned long long pol;
    asm("createpolicy.fractional.L2::evict_last.b64 %0, 1.0;" : "=l"(pol));
    return pol;
}
__device__ __forceinline__ float ldel_f(const float* p, unsigned long long pol) {
    float v;
    asm volatile("ld.global.L2::cache_hint.f32 %0, [%1], %2;"
                 : "=f"(v) : "l"(p), "l"(pol));
    return v;
}
__device__ __forceinline__ float2 ldel_f2(const float2* p, unsigned long long pol) {
    float2 v;
    asm volatile("ld.global.L2::cache_hint.v2.f32 {%0,%1}, [%2], %3;"
                 : "=f"(v.x), "=f"(v.y) : "l"(p), "l"(pol));
    return v;
}
__device__ __forceinline__ float4 ldel_f4(const float4* p, unsigned long long pol) {
    float4 v;
    asm volatile("ld.global.L2::cache_hint.v4.f32 {%0,%1,%2,%3}, [%4], %5;"
                 : "=f"(v.x), "=f"(v.y), "=f"(v.z), "=f"(v.w) : "l"(p), "l"(pol));
    return v;
}

// -------- zero aggc only (immediately before edge1's scatter: warms L2) --------
__global__ void k_zero() {
    int i = blockIdx.x * blockDim.x + threadIdx.x;
    if (i < NN / 2) ((float4*)g_aggc)[i] = make_float4(0.f, 0.f, 0.f, 0.f);
}

// -------- pass 1: scatter {x[src], 1} to aggc[dst], 4 edges/thread --------
__global__ void k_edge1(const int4* __restrict__ src4,
                        const int4* __restrict__ dst4,
                        const float* __restrict__ x) {
    int t = blockIdx.x * blockDim.x + threadIdx.x;
    if (t >= NE / 4) return;
    unsigned long long pol = mk_evict_last_policy();
    int4 s = ldcs_int4(&src4[t]);
    int4 d = ldcs_int4(&dst4[t]);
    float x0 = ldel_f(&x[s.x], pol);
    float x1 = ldel_f(&x[s.y], pol);
    float x2 = ldel_f(&x[s.z], pol);
    float x3 = ldel_f(&x[s.w], pol);
    red_add_v2(&g_aggc[d.x], x0, 1.0f);
    red_add_v2(&g_aggc[d.y], x1, 1.0f);
    red_add_v2(&g_aggc[d.z], x2, 1.0f);
    red_add_v2(&g_aggc[d.w], x3, 1.0f);
}

// -------- node 1: h1 = relu(mean1*W1l + b1 + x*W1r); zero sum2 (warm for edge2) --------
__global__ void k_node1(const float* __restrict__ x,
                        const float* __restrict__ W1l, const float* __restrict__ b1,
                        const float* __restrict__ W1r) {
    int i = blockIdx.x * blockDim.x + threadIdx.x;
    if (i >= NN) return;
    float2 ac = g_aggc[i];
    float inv = 1.0f / fmaxf(ac.y, 1.0f);
    g_inv[i] = inv;
    float m = ac.x * inv;
    float xi = x[i];
    float4 h;
    h.x = fmaxf(m * W1l[0] + b1[0] + xi * W1r[0], 0.f);
    h.y = fmaxf(m * W1l[1] + b1[1] + xi * W1r[1], 0.f);
    h.z = fmaxf(m * W1l[2] + b1[2] + xi * W1r[2], 0.f);
    h.w = fmaxf(m * W1l[3] + b1[3] + xi * W1r[3], 0.f);
    g_h1[i] = h;
    g_sum2[i] = make_float4(0.f, 0.f, 0.f, 0.f);
}

// -------- pass 2: sum2[dst] += h1[src], 4 edges/thread --------
__global__ void k_edge2(const int4* __restrict__ src4,
                        const int4* __restrict__ dst4) {
    int t = blockIdx.x * blockDim.x + threadIdx.x;
    if (t >= NE / 4) return;
    unsigned long long pol = mk_evict_last_policy();
    int4 s = ldcs_int4(&src4[t]);
    int4 d = ldcs_int4(&dst4[t]);
    float4 v0 = ldel_f4(&g_h1[s.x], pol);
    float4 v1 = ldel_f4(&g_h1[s.y], pol);
    float4 v2 = ldel_f4(&g_h1[s.z], pol);
    float4 v3 = ldel_f4(&g_h1[s.w], pol);
    red_add_v4(&g_sum2[d.x], v0);
    red_add_v4(&g_sum2[d.y], v1);
    red_add_v4(&g_sum2[d.z], v2);
    red_add_v4(&g_sum2[d.w], v3);
}

// -------- node 2: h2 = relu(mean2@W2l + b2 + h1@W2r); p3 = h2@W3l; zero sum3 --------
__global__ void k_node2(const float* __restrict__ W2l, const float* __restrict__ b2,
                        const float* __restrict__ W2r, const float* __restrict__ W3l) {
    int i = blockIdx.x * blockDim.x + threadIdx.x;
    if (i >= NN) return;
    float inv = g_inv[i];
    float4 s = g_sum2[i];
    float4 m = make_float4(s.x * inv, s.y * inv, s.z * inv, s.w * inv);
    float4 p = g_h1[i];
    float4 h;
    #pragma unroll
    for (int j = 0; j < 4; j++) {
        float v = b2[j];
        v += m.x * W2l[0 * 4 + j] + m.y * W2l[1 * 4 + j]
           + m.z * W2l[2 * 4 + j] + m.w * W2l[3 * 4 + j];
        v += p.x * W2r[0 * 4 + j] + p.y * W2r[1 * 4 + j]
           + p.z * W2r[2 * 4 + j] + p.w * W2r[3 * 4 + j];
        v = fmaxf(v, 0.f);
        ((float*)&h)[j] = v;
    }
    g_h2[i] = h;
    // project to dim 2 now so the edge pass scatters 8B instead of 16B
    float2 q;
    q.x = h.x * W3l[0 * 2 + 0] + h.y * W3l[1 * 2 + 0]
        + h.z * W3l[2 * 2 + 0] + h.w * W3l[3 * 2 + 0];
    q.y = h.x * W3l[0 * 2 + 1] + h.y * W3l[1 * 2 + 1]
        + h.z * W3l[2 * 2 + 1] + h.w * W3l[3 * 2 + 1];
    g_p3[i] = q;
    g_sum3[i] = make_float2(0.f, 0.f);
}

// -------- pass 3: sum3[dst] += p3[src] (dim 2), 4 edges/thread --------
__global__ void k_edge3(const int4* __restrict__ src4,
                        const int4* __restrict__ dst4) {
    int t = blockIdx.x * blockDim.x + threadIdx.x;
    if (t >= NE / 4) return;
    unsigned long long pol = mk_evict_last_policy();
    int4 s = ldcs_int4(&src4[t]);
    int4 d = ldcs_int4(&dst4[t]);
    float2 v0 = ldel_f2(&g_p3[s.x], pol);
    float2 v1 = ldel_f2(&g_p3[s.y], pol);
    float2 v2 = ldel_f2(&g_p3[s.z], pol);
    float2 v3 = ldel_f2(&g_p3[s.w], pol);
    red_add_v2(&g_sum3[d.x], v0.x, v0.y);
    red_add_v2(&g_sum3[d.y], v1.x, v1.y);
    red_add_v2(&g_sum3[d.z], v2.x, v2.y);
    red_add_v2(&g_sum3[d.w], v3.x, v3.y);
}

// -------- node 3: h3 = relu(mean3@W3l + b3 + h2@W3r); out = h3@Wc + bc --------
__global__ void k_node3(const float* __restrict__ b3,
                        const float* __restrict__ W3r,
                        const float* __restrict__ Wc, const float* __restrict__ bc,
                        float* __restrict__ out) {
    int i = blockIdx.x * blockDim.x + threadIdx.x;
    if (i >= NN) return;
    float inv = g_inv[i];
    float2 s = g_sum3[i];        // already projected through W3l
    float4 p = g_h2[i];
    float h3[2];
    #pragma unroll
    for (int j = 0; j < 2; j++) {
        float v = b3[j] + ((j == 0) ? s.x : s.y) * inv;
        v += p.x * W3r[0 * 2 + j] + p.y * W3r[1 * 2 + j]
           + p.z * W3r[2 * 2 + j] + p.w * W3r[3 * 2 + j];
        h3[j] = fmaxf(v, 0.f);
    }
    float2 o;
    o.x = h3[0] * Wc[0] + h3[1] * Wc[2] + bc[0];
    o.y = h3[0] * Wc[1] + h3[1] * Wc[3] + bc[1];
    // output layout: (out [NN,2], h3 [NN,2]) flattened in order
    ((float2*)out)[i] = o;
    ((float2*)out)[NN + i] = make_float2(h3[0], h3[1]);
}

extern "C" void kernel_launch(void* const* d_in, const int* in_sizes, int n_in,
                              void* d_out, int out_size) {
    const float* x   = (const float*)d_in[0];
    const int*   ei  = (const int*)d_in[1];   // int64 in reference -> delivered as int32 [2, E]
    const int4*  src4 = (const int4*)ei;
    const int4*  dst4 = (const int4*)(ei + NE);
    const float* W1l = (const float*)d_in[2];
    const float* b1  = (const float*)d_in[3];
    const float* W1r = (const float*)d_in[4];
    const float* W2l = (const float*)d_in[5];
    const float* b2  = (const float*)d_in[6];
    const float* W2r = (const float*)d_in[7];
    const float* W3l = (const float*)d_in[8];
    const float* b3  = (const float*)d_in[9];
    const float* W3r = (const float*)d_in[10];
    const float* Wc  = (const float*)d_in[11];
    const float* bc  = (const float*)d_in[12];
    float* out = (float*)d_out;

    const int BT  = 256;   // node kernels
    const int BTE = 512;   // edge kernels: fewer, longer-lived blocks
    const int gridN  = (NN + BT - 1) / BT;
    const int gridN2 = (NN / 2 + BT - 1) / BT;
    const int gridE4 = (NE / 4 + BTE - 1) / BTE;

    k_zero<<<gridN2, BT>>>();
    k_edge1<<<gridE4, BTE>>>(src4, dst4, x);
    k_node1<<<gridN, BT>>>(x, W1l, b1, W1r);
    k_edge2<<<gridE4, BTE>>>(src4, dst4);
    k_node2<<<gridN, BT>>>(W2l, b2, W2r, W3l);
    k_edge3<<<gridE4, BTE>>>(src4, dst4);
    k_node3<<<gridN, BT>>>(b3, W3r, Wc, bc, out);
}

// round 16
// speedup vs baseline: 1.0012x; 1.0012x over previous
#include <cuda_runtime.h>
#include <cuda_bf16.h>

#define NN 1000000
#define NE 16000000

// -------- scratch (device globals; no allocation allowed) --------
__device__ float2 g_aggc[NN];    // {sum of x[src], count}
__device__ float4 g_h1[NN];
__device__ float4 g_sum2[NN];
__device__ float4 g_h2[NN];
__device__ float2 g_p3[NN];      // h2 @ W3l (projected to dim 2 before scatter)
__device__ float2 g_sum3[NN];    // accumulated projected values
__device__ float  g_inv[NN];     // 1 / max(count, 1)

__device__ __forceinline__ void red_add_v2(float2* addr, float a, float b) {
    asm volatile("red.global.add.v2.f32 [%0], {%1, %2};"
                 :: "l"(addr), "f"(a), "f"(b) : "memory");
}
__device__ __forceinline__ void red_add_v4(float4* addr, float4 v) {
    asm volatile("red.global.add.v4.f32 [%0], {%1, %2, %3, %4};"
                 :: "l"(addr), "f"(v.x), "f"(v.y), "f"(v.z), "f"(v.w) : "memory");
}
// streaming (evict-first) load for the one-shot edge index stream
__device__ __forceinline__ int4 ldcs_int4(const int4* p) {
    int4 v;
    asm volatile("ld.global.cs.v4.s32 {%0,%1,%2,%3}, [%4];"
                 : "=r"(v.x), "=r"(v.y), "=r"(v.z), "=r"(v.w) : "l"(p));
    return v;
}
// L2 evict-last cache policy (valid for any width via cache_hint form)
__device__ __forceinline__ unsigned long long mk_evict_last_policy() {
    unsigned long long pol;
    asm("createpolicy.fractional.L2::evict_last.b64 %0, 1.0;" : "=l"(pol));
    return pol;
}
__device__ __forceinline__ float ldel_f(const float* p, unsigned long long pol) {
    float v;
    asm volatile("ld.global.L2::cache_hint.f32 %0, [%1], %2;"
                 : "=f"(v) : "l"(p), "l"(pol));
    return v;
}
__device__ __forceinline__ float2 ldel_f2(const float2* p, unsigned long long pol) {
    float2 v;
    asm volatile("ld.global.L2::cache_hint.v2.f32 {%0,%1}, [%2], %3;"
                 : "=f"(v.x), "=f"(v.y) : "l"(p), "l"(pol));
    return v;
}
__device__ __forceinline__ float4 ldel_f4(const float4* p, unsigned long long pol) {
    float4 v;
    asm volatile("ld.global.L2::cache_hint.v4.f32 {%0,%1,%2,%3}, [%4], %5;"
                 : "=f"(v.x), "=f"(v.y), "=f"(v.z), "=f"(v.w) : "l"(p), "l"(pol));
    return v;
}

// -------- zero aggc only (immediately before edge1's scatter: warms L2) --------
__global__ void k_zero() {
    int i = blockIdx.x * blockDim.x + threadIdx.x;
    if (i < NN / 2) ((float4*)g_aggc)[i] = make_float4(0.f, 0.f, 0.f, 0.f);
}

// -------- pass 1: scatter {x[src], 1} to aggc[dst], 4 edges/thread --------
__global__ void k_edge1(const int4* __restrict__ src4,
                        const int4* __restrict__ dst4,
                        const float* __restrict__ x) {
    int t = blockIdx.x * blockDim.x + threadIdx.x;
    if (t >= NE / 4) return;
    unsigned long long pol = mk_evict_last_policy();
    int4 s = ldcs_int4(&src4[t]);
    int4 d = ldcs_int4(&dst4[t]);
    float x0 = ldel_f(&x[s.x], pol);
    float x1 = ldel_f(&x[s.y], pol);
    float x2 = ldel_f(&x[s.z], pol);
    float x3 = ldel_f(&x[s.w], pol);
    red_add_v2(&g_aggc[d.x], x0, 1.0f);
    red_add_v2(&g_aggc[d.y], x1, 1.0f);
    red_add_v2(&g_aggc[d.z], x2, 1.0f);
    red_add_v2(&g_aggc[d.w], x3, 1.0f);
}

// -------- node 1: h1 = relu(mean1*W1l + b1 + x*W1r); zero sum2 (warm for edge2) --------
__global__ void k_node1(const float* __restrict__ x,
                        const float* __restrict__ W1l, const float* __restrict__ b1,
                        const float* __restrict__ W1r) {
    int i = blockIdx.x * blockDim.x + threadIdx.x;
    if (i >= NN) return;
    float2 ac = g_aggc[i];
    float inv = 1.0f / fmaxf(ac.y, 1.0f);
    g_inv[i] = inv;
    float m = ac.x * inv;
    float xi = x[i];
    float4 h;
    h.x = fmaxf(m * W1l[0] + b1[0] + xi * W1r[0], 0.f);
    h.y = fmaxf(m * W1l[1] + b1[1] + xi * W1r[1], 0.f);
    h.z = fmaxf(m * W1l[2] + b1[2] + xi * W1r[2], 0.f);
    h.w = fmaxf(m * W1l[3] + b1[3] + xi * W1r[3], 0.f);
    g_h1[i] = h;
    g_sum2[i] = make_float4(0.f, 0.f, 0.f, 0.f);
}

// -------- pass 2: sum2[dst] += h1[src], 4 edges/thread --------
__global__ void k_edge2(const int4* __restrict__ src4,
                        const int4* __restrict__ dst4) {
    int t = blockIdx.x * blockDim.x + threadIdx.x;
    if (t >= NE / 4) return;
    unsigned long long pol = mk_evict_last_policy();
    int4 s = ldcs_int4(&src4[t]);
    int4 d = ldcs_int4(&dst4[t]);
    float4 v0 = ldel_f4(&g_h1[s.x], pol);
    float4 v1 = ldel_f4(&g_h1[s.y], pol);
    float4 v2 = ldel_f4(&g_h1[s.z], pol);
    float4 v3 = ldel_f4(&g_h1[s.w], pol);
    red_add_v4(&g_sum2[d.x], v0);
    red_add_v4(&g_sum2[d.y], v1);
    red_add_v4(&g_sum2[d.z], v2);
    red_add_v4(&g_sum2[d.w], v3);
}

// -------- node 2: h2 = relu(mean2@W2l + b2 + h1@W2r); p3 = h2@W3l; zero sum3 --------
__global__ void k_node2(const float* __restrict__ W2l, const float* __restrict__ b2,
                        const float* __restrict__ W2r, const float* __restrict__ W3l) {
    int i = blockIdx.x * blockDim.x + threadIdx.x;
    if (i >= NN) return;
    float inv = g_inv[i];
    float4 s = g_sum2[i];
    float4 m = make_float4(s.x * inv, s.y * inv, s.z * inv, s.w * inv);
    float4 p = g_h1[i];
    float4 h;
    #pragma unroll
    for (int j = 0; j < 4; j++) {
        float v = b2[j];
        v += m.x * W2l[0 * 4 + j] + m.y * W2l[1 * 4 + j]
           + m.z * W2l[2 * 4 + j] + m.w * W2l[3 * 4 + j];
        v += p.x * W2r[0 * 4 + j] + p.y * W2r[1 * 4 + j]
           + p.z * W2r[2 * 4 + j] + p.w * W2r[3 * 4 + j];
        v = fmaxf(v, 0.f);
        ((float*)&h)[j] = v;
    }
    g_h2[i] = h;
    // project to dim 2 now so the edge pass scatters 8B instead of 16B
    float2 q;
    q.x = h.x * W3l[0 * 2 + 0] + h.y * W3l[1 * 2 + 0]
        + h.z * W3l[2 * 2 + 0] + h.w * W3l[3 * 2 + 0];
    q.y = h.x * W3l[0 * 2 + 1] + h.y * W3l[1 * 2 + 1]
        + h.z * W3l[2 * 2 + 1] + h.w * W3l[3 * 2 + 1];
    g_p3[i] = q;
    g_sum3[i] = make_float2(0.f, 0.f);
}

// -------- pass 3: sum3[dst] += p3[src] (dim 2), 4 edges/thread --------
__global__ void k_edge3(const int4* __restrict__ src4,
                        const int4* __restrict__ dst4) {
    int t = blockIdx.x * blockDim.x + threadIdx.x;
    if (t >= NE / 4) return;
    unsigned long long pol = mk_evict_last_policy();
    int4 s = ldcs_int4(&src4[t]);
    int4 d = ldcs_int4(&dst4[t]);
    float2 v0 = ldel_f2(&g_p3[s.x], pol);
    float2 v1 = ldel_f2(&g_p3[s.y], pol);
    float2 v2 = ldel_f2(&g_p3[s.z], pol);
    float2 v3 = ldel_f2(&g_p3[s.w], pol);
    red_add_v2(&g_sum3[d.x], v0.x, v0.y);
    red_add_v2(&g_sum3[d.y], v1.x, v1.y);
    red_add_v2(&g_sum3[d.z], v2.x, v2.y);
    red_add_v2(&g_sum3[d.w], v3.x, v3.y);
}

// -------- node 3: h3 = relu(mean3@W3l + b3 + h2@W3r); out = h3@Wc + bc --------
__global__ void k_node3(const float* __restrict__ b3,
                        const float* __restrict__ W3r,
                        const float* __restrict__ Wc, const float* __restrict__ bc,
                        float* __restrict__ out) {
    int i = blockIdx.x * blockDim.x + threadIdx.x;
    if (i >= NN) return;
    float inv = g_inv[i];
    float2 s = g_sum3[i];        // already projected through W3l
    float4 p = g_h2[i];
    float h3[2];
    #pragma unroll
    for (int j = 0; j < 2; j++) {
        float v = b3[j] + ((j == 0) ? s.x : s.y) * inv;
        v += p.x * W3r[0 * 2 + j] + p.y * W3r[1 * 2 + j]
           + p.z * W3r[2 * 2 + j] + p.w * W3r[3 * 2 + j];
        h3[j] = fmaxf(v, 0.f);
    }
    float2 o;
    o.x = h3[0] * Wc[0] + h3[1] * Wc[2] + bc[0];
    o.y = h3[0] * Wc[1] + h3[1] * Wc[3] + bc[1];
    // output layout: (out [NN,2], h3 [NN,2]) flattened in order
    ((float2*)out)[i] = o;
    ((float2*)out)[NN + i] = make_float2(h3[0], h3[1]);
}

extern "C" void kernel_launch(void* const* d_in, const int* in_sizes, int n_in,
                              void* d_out, int out_size) {
    const float* x   = (const float*)d_in[0];
    const int*   ei  = (const int*)d_in[1];   // int64 in reference -> delivered as int32 [2, E]
    const int4*  src4 = (const int4*)ei;
    const int4*  dst4 = (const int4*)(ei + NE);
    const float* W1l = (const float*)d_in[2];
    const float* b1  = (const float*)d_in[3];
    const float* W1r = (const float*)d_in[4];
    const float* W2l = (const float*)d_in[5];
    const float* b2  = (const float*)d_in[6];
    const float* W2r = (const float*)d_in[7];
    const float* W3l = (const float*)d_in[8];
    const float* b3  = (const float*)d_in[9];
    const float* W3r = (const float*)d_in[10];
    const float* Wc  = (const float*)d_in[11];
    const float* bc  = (const float*)d_in[12];
    float* out = (float*)d_out;

    const int BT = 256;
    const int gridN  = (NN + BT - 1) / BT;
    const int gridN2 = (NN / 2 + BT - 1) / BT;
    const int gridE4 = (NE / 4 + BT - 1) / BT;

    k_zero<<<gridN2, BT>>>();
    k_edge1<<<gridE4, BT>>>(src4, dst4, x);
    k_node1<<<gridN, BT>>>(x, W1l, b1, W1r);
    k_edge2<<<gridE4, BT>>>(src4, dst4);
    k_node2<<<gridN, BT>>>(W2l, b2, W2r, W3l);
    k_edge3<<<gridE4, BT>>>(src4, dst4);
    k_node3<<<gridN, BT>>>(b3, W3r, Wc, bc, out);
}

// round 17
// speedup vs baseline: 1.0065x; 1.0053x over previous
#include <cuda_runtime.h>
#include <cuda_bf16.h>

#define NN 1000000
#define NE 16000000

// -------- scratch (device globals; no allocation allowed) --------
__device__ float2 g_aggc[NN];    // {sum of x[src], count}
__device__ float4 g_h1[NN];
__device__ float4 g_sum2[NN];
__device__ float4 g_h2[NN];
__device__ float2 g_p3[NN];      // h2 @ W3l (projected to dim 2 before scatter)
__device__ float2 g_sum3[NN];    // accumulated projected values
__device__ float  g_inv[NN];     // 1 / max(count, 1)

__device__ __forceinline__ void red_add_v2(float2* addr, float a, float b) {
    asm volatile("red.global.add.v2.f32 [%0], {%1, %2};"
                 :: "l"(addr), "f"(a), "f"(b) : "memory");
}
__device__ __forceinline__ void red_add_v4(float4* addr, float4 v) {
    asm volatile("red.global.add.v4.f32 [%0], {%1, %2, %3, %4};"
                 :: "l"(addr), "f"(v.x), "f"(v.y), "f"(v.z), "f"(v.w) : "memory");
}
// streaming (evict-first) load for the one-shot edge index stream
__device__ __forceinline__ int4 ldcs_int4(const int4* p) {
    int4 v;
    asm volatile("ld.global.cs.v4.s32 {%0,%1,%2,%3}, [%4];"
                 : "=r"(v.x), "=r"(v.y), "=r"(v.z), "=r"(v.w) : "l"(p));
    return v;
}
// L2 evict-last cache policy (valid for any width via cache_hint form)
__device__ __forceinline__ unsigned long long mk_evict_last_policy() {
    unsigned long long pol;
    asm("createpolicy.fractional.L2::evict_last.b64 %0, 1.0;" : "=l"(pol));
    return pol;
}
__device__ __forceinline__ float ldel_f(const float* p, unsigned long long pol) {
    float v;
    asm volatile("ld.global.L2::cache_hint.f32 %0, [%1], %2;"
                 : "=f"(v) : "l"(p), "l"(pol));
    return v;
}
__device__ __forceinline__ float2 ldel_f2(const float2* p, unsigned long long pol) {
    float2 v;
    asm volatile("ld.global.L2::cache_hint.v2.f32 {%0,%1}, [%2], %3;"
                 : "=f"(v.x), "=f"(v.y) : "l"(p), "l"(pol));
    return v;
}
__device__ __forceinline__ float4 ldel_f4(const float4* p, unsigned long long pol) {
    float4 v;
    asm volatile("ld.global.L2::cache_hint.v4.f32 {%0,%1,%2,%3}, [%4], %5;"
                 : "=f"(v.x), "=f"(v.y), "=f"(v.z), "=f"(v.w) : "l"(p), "l"(pol));
    return v;
}

// -------- zero aggc only (immediately before edge1's scatter: warms L2) --------
__global__ void k_zero() {
    int i = blockIdx.x * blockDim.x + threadIdx.x;
    if (i < NN / 2) ((float4*)g_aggc)[i] = make_float4(0.f, 0.f, 0.f, 0.f);
}

// -------- pass 1: scatter {x[src], 1} to aggc[dst], 4 edges/thread --------
__global__ void k_edge1(const int4* __restrict__ src4,
                        const int4* __restrict__ dst4,
                        const float* __restrict__ x) {
    int t = blockIdx.x * blockDim.x + threadIdx.x;
    if (t >= NE / 4) return;
    unsigned long long pol = mk_evict_last_policy();
    int4 s = ldcs_int4(&src4[t]);
    int4 d = ldcs_int4(&dst4[t]);
    float x0 = ldel_f(&x[s.x], pol);
    float x1 = ldel_f(&x[s.y], pol);
    float x2 = ldel_f(&x[s.z], pol);
    float x3 = ldel_f(&x[s.w], pol);
    red_add_v2(&g_aggc[d.x], x0, 1.0f);
    red_add_v2(&g_aggc[d.y], x1, 1.0f);
    red_add_v2(&g_aggc[d.z], x2, 1.0f);
    red_add_v2(&g_aggc[d.w], x3, 1.0f);
}

// -------- node 1: h1 = relu(mean1*W1l + b1 + x*W1r); zero sum2 (warm for edge2) --------
__global__ void k_node1(const float* __restrict__ x,
                        const float* __restrict__ W1l, const float* __restrict__ b1,
                        const float* __restrict__ W1r) {
    int i = blockIdx.x * blockDim.x + threadIdx.x;
    if (i >= NN) return;
    float2 ac = g_aggc[i];
    float inv = 1.0f / fmaxf(ac.y, 1.0f);
    g_inv[i] = inv;
    float m = ac.x * inv;
    float xi = x[i];
    float4 h;
    h.x = fmaxf(m * W1l[0] + b1[0] + xi * W1r[0], 0.f);
    h.y = fmaxf(m * W1l[1] + b1[1] + xi * W1r[1], 0.f);
    h.z = fmaxf(m * W1l[2] + b1[2] + xi * W1r[2], 0.f);
    h.w = fmaxf(m * W1l[3] + b1[3] + xi * W1r[3], 0.f);
    g_h1[i] = h;
    g_sum2[i] = make_float4(0.f, 0.f, 0.f, 0.f);
}

// -------- pass 2: sum2[dst] += h1[src], 4 edges/thread --------
__global__ void k_edge2(const int4* __restrict__ src4,
                        const int4* __restrict__ dst4) {
    int t = blockIdx.x * blockDim.x + threadIdx.x;
    if (t >= NE / 4) return;
    unsigned long long pol = mk_evict_last_policy();
    int4 s = ldcs_int4(&src4[t]);
    int4 d = ldcs_int4(&dst4[t]);
    float4 v0 = ldel_f4(&g_h1[s.x], pol);
    float4 v1 = ldel_f4(&g_h1[s.y], pol);
    float4 v2 = ldel_f4(&g_h1[s.z], pol);
    float4 v3 = ldel_f4(&g_h1[s.w], pol);
    red_add_v4(&g_sum2[d.x], v0);
    red_add_v4(&g_sum2[d.y], v1);
    red_add_v4(&g_sum2[d.z], v2);
    red_add_v4(&g_sum2[d.w], v3);
}

// -------- node 2: h2 = relu(mean2@W2l + b2 + h1@W2r); p3 = h2@W3l; zero sum3 --------
__global__ void k_node2(const float* __restrict__ W2l, const float* __restrict__ b2,
                        const float* __restrict__ W2r, const float* __restrict__ W3l) {
    int i = blockIdx.x * blockDim.x + threadIdx.x;
    if (i >= NN) return;
    float inv = g_inv[i];
    float4 s = g_sum2[i];
    float4 m = make_float4(s.x * inv, s.y * inv, s.z * inv, s.w * inv);
    float4 p = g_h1[i];
    float4 h;
    #pragma unroll
    for (int j = 0; j < 4; j++) {
        float v = b2[j];
        v += m.x * W2l[0 * 4 + j] + m.y * W2l[1 * 4 + j]
           + m.z * W2l[2 * 4 + j] + m.w * W2l[3 * 4 + j];
        v += p.x * W2r[0 * 4 + j] + p.y * W2r[1 * 4 + j]
           + p.z * W2r[2 * 4 + j] + p.w * W2r[3 * 4 + j];
        v = fmaxf(v, 0.f);
        ((float*)&h)[j] = v;
    }
    g_h2[i] = h;
    // project to dim 2 now so the edge pass scatters 8B instead of 16B
    float2 q;
    q.x = h.x * W3l[0 * 2 + 0] + h.y * W3l[1 * 2 + 0]
        + h.z * W3l[2 * 2 + 0] + h.w * W3l[3 * 2 + 0];
    q.y = h.x * W3l[0 * 2 + 1] + h.y * W3l[1 * 2 + 1]
        + h.z * W3l[2 * 2 + 1] + h.w * W3l[3 * 2 + 1];
    g_p3[i] = q;
    g_sum3[i] = make_float2(0.f, 0.f);
}

// -------- pass 3: sum3[dst] += p3[src] (dim 2), 4 edges/thread --------
__global__ void k_edge3(const int4* __restrict__ src4,
                        const int4* __restrict__ dst4) {
    int t = blockIdx.x * blockDim.x + threadIdx.x;
    if (t >= NE / 4) return;
    unsigned long long pol = mk_evict_last_policy();
    int4 s = ldcs_int4(&src4[t]);
    int4 d = ldcs_int4(&dst4[t]);
    float2 v0 = ldel_f2(&g_p3[s.x], pol);
    float2 v1 = ldel_f2(&g_p3[s.y], pol);
    float2 v2 = ldel_f2(&g_p3[s.z], pol);
    float2 v3 = ldel_f2(&g_p3[s.w], pol);
    red_add_v2(&g_sum3[d.x], v0.x, v0.y);
    red_add_v2(&g_sum3[d.y], v1.x, v1.y);
    red_add_v2(&g_sum3[d.z], v2.x, v2.y);
    red_add_v2(&g_sum3[d.w], v3.x, v3.y);
}

// -------- node 3: h3 = relu(mean3@W3l + b3 + h2@W3r); out = h3@Wc + bc --------
__global__ void k_node3(const float* __restrict__ b3,
                        const float* __restrict__ W3r,
                        const float* __restrict__ Wc, const float* __restrict__ bc,
                        float* __restrict__ out) {
    int i = blockIdx.x * blockDim.x + threadIdx.x;
    if (i >= NN) return;
    float inv = g_inv[i];
    float2 s = g_sum3[i];        // already projected through W3l
    float4 p = g_h2[i];
    float h3[2];
    #pragma unroll
    for (int j = 0; j < 2; j++) {
        float v = b3[j] + ((j == 0) ? s.x : s.y) * inv;
        v += p.x * W3r[0 * 2 + j] + p.y * W3r[1 * 2 + j]
           + p.z * W3r[2 * 2 + j] + p.w * W3r[3 * 2 + j];
        h3[j] = fmaxf(v, 0.f);
    }
    float2 o;
    o.x = h3[0] * Wc[0] + h3[1] * Wc[2] + bc[0];
    o.y = h3[0] * Wc[1] + h3[1] * Wc[3] + bc[1];
    // output layout: (out [NN,2], h3 [NN,2]) flattened in order
    ((float2*)out)[i] = o;
    ((float2*)out)[NN + i] = make_float2(h3[0], h3[1]);
}

extern "C" void kernel_launch(void* const* d_in, const int* in_sizes, int n_in,
                              void* d_out, int out_size) {
    const float* x   = (const float*)d_in[0];
    const int*   ei  = (const int*)d_in[1];   // int64 in reference -> delivered as int32 [2, E]
    const int4*  src4 = (const int4*)ei;
    const int4*  dst4 = (const int4*)(ei + NE);
    const float* W1l = (const float*)d_in[2];
    const float* b1  = (const float*)d_in[3];
    const float* W1r = (const float*)d_in[4];
    const float* W2l = (const float*)d_in[5];
    const float* b2  = (const float*)d_in[6];
    const float* W2r = (const float*)d_in[7];
    const float* W3l = (const float*)d_in[8];
    const float* b3  = (const float*)d_in[9];
    const float* W3r = (const float*)d_in[10];
    const float* Wc  = (const float*)d_in[11];
    const float* bc  = (const float*)d_in[12];
    float* out = (float*)d_out;

    const int BT = 256;
    const int gridN  = (NN + BT - 1) / BT;
    const int gridN2 = (NN / 2 + BT - 1) / BT;
    const int gridE4 = (NE / 4 + BT - 1) / BT;

    k_zero<<<gridN2, BT>>>();
    k_edge1<<<gridE4, BT>>>(src4, dst4, x);
    k_node1<<<gridN, BT>>>(x, W1l, b1, W1r);
    k_edge2<<<gridE4, BT>>>(src4, dst4);
    k_node2<<<gridN, BT>>>(W2l, b2, W2r, W3l);
    k_edge3<<<gridE4, BT>>>(src4, dst4);
    k_node3<<<gridN, BT>>>(b3, W3r, Wc, bc, out);
}